// round 1
// baseline (speedup 1.0000x reference)
#include <cuda_runtime.h>
#include <math.h>

// Problem constants
#define BB    2
#define LL    144
#define DIN   1024
#define DT    150
#define NOUT  4
#define BL    288            // B*L
#define BZO   1152           // B*L*NOUT
#define OI    600            // NOUT*DT
#define WSTRIDE 22500        // DT*DT
#define TSTRIDE 21600        // DT*LL
#define PROJN   43200        // BL*DT
#define OUT1N   23887872     // B*L*L*L*NOUT
#define PEROUT  5971968      // B*L*L*L  (4-tuples per output)
#define TOT4    11943936     // 2*PEROUT

// Scratch (device globals; no runtime allocation)
__device__ float g_proj[4][PROJN];          // 0:sh 1:st 2:oh 3:ot
__device__ float g_w[BZO * WSTRIDE];        // [bz][o][i][j]  (103.7 MB)
__device__ float g_t[BZO * TSTRIDE];        // [bzo][i][y]    (99.5 MB)

// ---------------------------------------------------------------------------
// Generic tiled fp32 GEMM, 48x48 tile, BK=16, 64 threads, 6x6 micro-tile.
// MODE 0: proj        C=g_proj[sel] : x(288x1024) @ W(1024x150) + bias
// MODE 1: op1         C=g_w        : sh(288x150) @ Wtri[p](150x150), p=o*150+i
// MODE 2: op2         C=g_t        : g_w[p](150x150) @ Y[b]^T (Y 144x150), p=bzo
// MODE 3: op3 (tri1)  C=out        : X[b](144x150) @ g_t[p](150x144), direct store
// MODE 4: op3 (tri2)  C=out        : same, transposed (x<->y) store
// ---------------------------------------------------------------------------
template<int MODE>
__global__ __launch_bounds__(64)
void gemm48(const float* __restrict__ A0, const float* __restrict__ B0,
            float* __restrict__ C0, const float* __restrict__ bias, int sel)
{
    constexpr int BM = 48, BN = 48, BK = 16;

    int M, N, K, lda, ldb;
    if constexpr (MODE == 0) { M = BL;  N = DT; K = DIN; lda = DIN; ldb = DT; }
    if constexpr (MODE == 1) { M = BL;  N = DT; K = DT;  lda = DT;  ldb = DT; }
    if constexpr (MODE == 2) { M = DT;  N = LL; K = DT;  lda = DT;  ldb = DT; }
    if constexpr (MODE == 3 || MODE == 4) { M = LL; N = LL; K = DT; lda = DT; ldb = LL; }

    const int p = blockIdx.z;
    const float* A;
    const float* Bm;
    if constexpr (MODE == 0) { A = A0;                 Bm = B0; }
    if constexpr (MODE == 1) { A = g_proj[0];          Bm = B0 + p * WSTRIDE; }
    if constexpr (MODE == 2) { int b = p / 576; A = g_w + (size_t)p * WSTRIDE; Bm = g_proj[sel] + b * TSTRIDE; }
    if constexpr (MODE == 3 || MODE == 4) { int b = p / 576; A = g_proj[sel] + b * TSTRIDE; Bm = g_t + (size_t)p * TSTRIDE; }

    __shared__ float As[BK][BM];
    __shared__ float Bs[BK][BN];

    const int tid = threadIdx.x;
    const int tm  = tid >> 3;   // 0..7
    const int tn  = tid & 7;    // 0..7
    const int m0  = blockIdx.x * BM;
    const int n0  = blockIdx.y * BN;

    float acc[6][6];
    #pragma unroll
    for (int u = 0; u < 6; u++)
        #pragma unroll
        for (int v = 0; v < 6; v++) acc[u][v] = 0.f;

    const int kTiles = (K + BK - 1) / BK;
    for (int kt = 0; kt < kTiles; kt++) {
        const int k0 = kt * BK;

        // --- load A tile (48 rows x 16 k) as float2 along k, store transposed
        #pragma unroll
        for (int i = tid; i < 384; i += 64) {
            int m  = i >> 3;
            int kk = (i & 7) * 2;
            int gm = m0 + m, gk = k0 + kk;
            float vx = 0.f, vy = 0.f;
            if (gm < M && gk < K) {
                const float* ap = A + (size_t)gm * lda + gk;
                if (gk + 1 < K) { float2 t2 = *(const float2*)ap; vx = t2.x; vy = t2.y; }
                else            { vx = *ap; }
            }
            As[kk][m] = vx; As[kk + 1][m] = vy;
        }

        // --- load B tile
        if constexpr (MODE == 2) {
            // B logical (K x N) = Y^T :  Bs[kk][n] = Y[n*ldb + k]
            #pragma unroll
            for (int i = tid; i < 384; i += 64) {
                int n  = i >> 3;
                int kk = (i & 7) * 2;
                int gn = n0 + n, gk = k0 + kk;
                float vx = 0.f, vy = 0.f;
                if (gn < N && gk < K) {
                    const float* bp = Bm + (size_t)gn * ldb + gk;
                    if (gk + 1 < K) { float2 t2 = *(const float2*)bp; vx = t2.x; vy = t2.y; }
                    else            { vx = *bp; }
                }
                Bs[kk][n] = vx; Bs[kk + 1][n] = vy;
            }
        } else {
            // normal: Bs[kk][n] = B[(k0+kk)*ldb + n0+n]
            #pragma unroll
            for (int i = tid; i < 384; i += 64) {
                int kk = i / 24;
                int n  = (i % 24) * 2;
                int gk = k0 + kk, gn = n0 + n;
                float vx = 0.f, vy = 0.f;
                if (gk < K && gn < N) {
                    const float* bp = Bm + (size_t)gk * ldb + gn;
                    if (gn + 1 < N) { float2 t2 = *(const float2*)bp; vx = t2.x; vy = t2.y; }
                    else            { vx = *bp; }
                }
                Bs[kk][n] = vx; Bs[kk][n + 1] = vy;
            }
        }
        __syncthreads();

        #pragma unroll
        for (int kk = 0; kk < BK; kk++) {
            float a[6], b[6];
            #pragma unroll
            for (int u = 0; u < 6; u++) a[u] = As[kk][tm * 6 + u];
            #pragma unroll
            for (int v = 0; v < 6; v++) b[v] = Bs[kk][tn * 6 + v];
            #pragma unroll
            for (int u = 0; u < 6; u++)
                #pragma unroll
                for (int v = 0; v < 6; v++) acc[u][v] += a[u] * b[v];
        }
        __syncthreads();
    }

    // --- store
    #pragma unroll
    for (int u = 0; u < 6; u++) {
        int gm = m0 + tm * 6 + u;
        if (gm >= M) continue;
        #pragma unroll
        for (int v = 0; v < 6; v++) {
            int gn = n0 + tn * 6 + v;
            if (gn >= N) continue;
            float val = acc[u][v];
            if constexpr (MODE == 0) {
                g_proj[sel][gm * DT + gn] = val + bias[gn];
            }
            if constexpr (MODE == 1) {
                // C[m=bz][n=j] -> g_w[bz*90000 + p*150 + j]
                g_w[(size_t)gm * (NOUT * WSTRIDE) + p * DT + gn] = val;
            }
            if constexpr (MODE == 2) {
                g_t[(size_t)p * TSTRIDE + gm * LL + gn] = val;
            }
            if constexpr (MODE == 3) {
                int bz = p >> 2, o = p & 3;
                C0[(((size_t)bz * LL + gm) * LL + gn) * NOUT + o] = val;
            }
            if constexpr (MODE == 4) {
                int bz = p >> 2, o = p & 3;
                C0[(((size_t)bz * LL + gn) * LL + gm) * NOUT + o] = val;
            }
        }
    }
}

// ---------------------------------------------------------------------------
// Epilogue: mask (z<=x keep, else constant) + log_softmax over NOUT=4,
// in-place on d_out (both concatenated outputs).
// ---------------------------------------------------------------------------
__global__ void epilogue_kernel(float* __restrict__ out)
{
    int e = blockIdx.x * blockDim.x + threadIdx.x;
    if (e >= TOT4) return;
    int r = e % PEROUT;
    int x = (r / LL) % LL;
    int z = (r / (LL * LL)) % LL;

    float4* p4 = (float4*)out;
    float4 v = p4[e];
    if (z > x) {
        const float c = -1.3862943611198906f;   // log(1/4)
        v.x = c; v.y = c; v.z = c; v.w = c;
    } else {
        float m = fmaxf(fmaxf(v.x, v.y), fmaxf(v.z, v.w));
        float s = expf(v.x - m) + expf(v.y - m) + expf(v.z - m) + expf(v.w - m);
        float l = m + logf(s);
        v.x -= l; v.y -= l; v.z -= l; v.w -= l;
    }
    p4[e] = v;
}

// ---------------------------------------------------------------------------
extern "C" void kernel_launch(void* const* d_in, const int* in_sizes, int n_in,
                              void* d_out, int out_size)
{
    const float* x     = (const float*)d_in[0];
    const float* W_sh  = (const float*)d_in[1];
    const float* b_sh  = (const float*)d_in[2];
    const float* W_st  = (const float*)d_in[3];
    const float* b_st  = (const float*)d_in[4];
    const float* W_oh  = (const float*)d_in[5];
    const float* b_oh  = (const float*)d_in[6];
    const float* W_ot  = (const float*)d_in[7];
    const float* b_ot  = (const float*)d_in[8];
    const float* W_t1  = (const float*)d_in[9];
    const float* W_t2  = (const float*)d_in[10];
    float* out = (float*)d_out;

    // 1) projections: sh, st, oh, ot  (MODE 0)
    dim3 gProj(6, 4, 1);  // ceil(288/48), ceil(150/48)
    gemm48<0><<<gProj, 64>>>(x, W_sh, nullptr, b_sh, 0);
    gemm48<0><<<gProj, 64>>>(x, W_st, nullptr, b_st, 1);
    gemm48<0><<<gProj, 64>>>(x, W_oh, nullptr, b_oh, 2);
    gemm48<0><<<gProj, 64>>>(x, W_ot, nullptr, b_ot, 3);

    dim3 gOp1(6, 4, OI);    // M=288, N=150, batch 600
    dim3 gOp2(4, 3, BZO);   // M=150, N=144, batch 1152
    dim3 gOp3(3, 3, BZO);   // M=144, N=144, batch 1152

    // 2) triaffine 1:  (x=st, y=oh, z=sh, W1) -> out[0:OUT1N]
    gemm48<1><<<gOp1, 64>>>(nullptr, W_t1, nullptr, nullptr, 0);
    gemm48<2><<<gOp2, 64>>>(nullptr, nullptr, nullptr, nullptr, 2); // Y = oh
    gemm48<3><<<gOp3, 64>>>(nullptr, nullptr, out, nullptr, 1);     // X = st

    // 3) triaffine 2:  (x=ot, y=st, z=sh, W2) -> transposed store into out[OUT1N:]
    gemm48<1><<<gOp1, 64>>>(nullptr, W_t2, nullptr, nullptr, 0);
    gemm48<2><<<gOp2, 64>>>(nullptr, nullptr, nullptr, nullptr, 1); // Y = st
    gemm48<4><<<gOp3, 64>>>(nullptr, nullptr, out + OUT1N, nullptr, 3); // X = ot

    // 4) mask + log_softmax epilogue, in place
    epilogue_kernel<<<(TOT4 + 255) / 256, 256>>>(out);
}

// round 2
// speedup vs baseline: 1.9577x; 1.9577x over previous
#include <cuda_runtime.h>
#include <cuda_bf16.h>
#include <math.h>
#include <stdint.h>

// ---------------- problem constants ----------------
#define BB    2
#define LLn   144
#define DIN   1024
#define DT    150
#define DTP   160            // DT padded to multiple of 16
#define NOUT  4
#define BL    288            // B*L
#define BZO   1152           // B*L*NOUT
#define OI    600            // NOUT*DT
#define OUT1N 23887872       // B*L*L*L*NOUT
#define PEROUT 5971968       // B*L*L*L
#define TOT4   11943936      // 2*PEROUT

// ---------------- scratch (device globals, bf16 hi/lo splits) -------------
__device__ __align__(256) __nv_bfloat16 g_xh[BL*DIN],        g_xl[BL*DIN];
__device__ __align__(256) __nv_bfloat16 g_Wph[4][DT*DIN],    g_Wpl[4][DT*DIN];   // [sel][n][k]
__device__ __align__(256) __nv_bfloat16 g_Wth[2][OI*DT*DTP], g_Wtl[2][OI*DT*DTP];// [tri][oi][j][k]
__device__ __align__(256) __nv_bfloat16 g_ph[4][BL*DTP],     g_pl[4][BL*DTP];    // projections
__device__ __align__(256) __nv_bfloat16 g_wh[BZO*DT*DTP],    g_wl[BZO*DT*DTP];   // [bz,o][i][j]
__device__ __align__(256) __nv_bfloat16 g_th[BZO*LLn*DTP],   g_tl[BZO*LLn*DTP];  // [bz,o][y][i]

// ---------------- helpers ----------------
__device__ __forceinline__ void split2(float v, __nv_bfloat16& h, __nv_bfloat16& l) {
    h = __float2bfloat16_rn(v);
    l = __float2bfloat16_rn(v - __bfloat162float(h));
}

__device__ __forceinline__ void ldm4(uint32_t* d, uint32_t addr) {
    asm volatile("ldmatrix.sync.aligned.m8n8.x4.shared.b16 {%0,%1,%2,%3}, [%4];"
        : "=r"(d[0]), "=r"(d[1]), "=r"(d[2]), "=r"(d[3]) : "r"(addr));
}

__device__ __forceinline__ void mma_bf16(float* c, const uint32_t* a, uint32_t b0, uint32_t b1) {
    asm volatile("mma.sync.aligned.m16n8k16.row.col.f32.bf16.bf16.f32 "
        "{%0,%1,%2,%3}, {%4,%5,%6,%7}, {%8,%9}, {%0,%1,%2,%3};"
        : "+f"(c[0]), "+f"(c[1]), "+f"(c[2]), "+f"(c[3])
        : "r"(a[0]), "r"(a[1]), "r"(a[2]), "r"(a[3]), "r"(b0), "r"(b1));
}

// ---------------- prep kernels ----------------
__global__ void prep_x(const float* __restrict__ x) {
    int i = blockIdx.x * 256 + threadIdx.x;
    if (i >= BL * DIN) return;
    split2(x[i], g_xh[i], g_xl[i]);
}

// proj weights: [k=1024][n=150] -> [n][k] hi/lo
__global__ void prep_pw(const float* __restrict__ W, int sel) {
    int i = blockIdx.x * 256 + threadIdx.x;
    if (i >= DT * DIN) return;
    int n = i >> 10, k = i & 1023;
    split2(__ldg(&W[k * DT + n]), g_Wph[sel][i], g_Wpl[sel][i]);
}

// W_tri: [oi][k=150][j=150] -> [oi][j=150][k=160(pad0)] hi/lo, tiled transpose
__global__ void prep_wt(const float* __restrict__ W, int tri) {
    __shared__ float t[32][33];
    int oi = blockIdx.x;
    int kt = blockIdx.y * 32, jt = blockIdx.z * 32;
    int tx = threadIdx.x, ty = threadIdx.y;
    int k = kt + ty, j = jt + tx;
    float v = (k < DT && j < DT) ? W[(size_t)oi * (DT * DT) + k * DT + j] : 0.f;
    t[ty][tx] = v;
    __syncthreads();
    int j2 = jt + ty, k2 = kt + tx;
    if (j2 < DT && k2 < DTP) {
        float u = t[tx][ty];
        size_t d = (size_t)oi * (DT * DTP) + (size_t)j2 * DTP + k2;
        split2(u, g_Wth[tri][d], g_Wtl[tri][d]);
    }
}

// ---------------- mma GEMM: BM=BN=48, BK=16, 96 threads (3 warps) ----------
// MODE 0: proj   C=g_p[sel]  : x(288xK1024) @ Wp[sel]   ; store hi/lo +bias
// MODE 1: op1    C=g_w       : sh(288x160) @ Wt[tri][oi]; p=oi, store [bz,o,i,j]
// MODE 2: op2    C=g_t       : Y(144x160) @ w[p]^T      ; p=bzo, store [p,y,i]
// MODE 3: op3/t1 C=out       : X(144x160) @ t[p]^T      ; direct store
// MODE 4: op3/t2 C=out       : same, transposed (x<->y) store
template<int MODE>
__global__ __launch_bounds__(96)
void mmak(const float* __restrict__ bias, float* __restrict__ outp, int sel, int tri)
{
    __shared__ __align__(16) unsigned char sm[9216];  // A: [2][48][24] bf16, B same at +4608

    const int tid = threadIdx.x;
    const int p = blockIdx.z;

    const __nv_bfloat16 *Ah, *Al, *Bh, *Bl;
    int lda, ldb, kT, NB;
    if constexpr (MODE == 0) {
        Ah = g_xh; Al = g_xl; Bh = g_Wph[sel]; Bl = g_Wpl[sel];
        lda = DIN; ldb = DIN; kT = 64; NB = DT;
    }
    if constexpr (MODE == 1) {
        Ah = g_ph[0]; Al = g_pl[0];
        Bh = g_Wth[tri] + (size_t)p * (DT * DTP);
        Bl = g_Wtl[tri] + (size_t)p * (DT * DTP);
        lda = DTP; ldb = DTP; kT = 10; NB = DT;
    }
    if constexpr (MODE == 2) {
        int b = p / (LLn * NOUT);
        Ah = g_ph[sel] + (size_t)b * (LLn * DTP);
        Al = g_pl[sel] + (size_t)b * (LLn * DTP);
        Bh = g_wh + (size_t)p * (DT * DTP);
        Bl = g_wl + (size_t)p * (DT * DTP);
        lda = DTP; ldb = DTP; kT = 10; NB = DT;
    }
    if constexpr (MODE >= 3) {
        int b = p / (LLn * NOUT);
        Ah = g_ph[sel] + (size_t)b * (LLn * DTP);
        Al = g_pl[sel] + (size_t)b * (LLn * DTP);
        Bh = g_th + (size_t)p * (LLn * DTP);
        Bl = g_tl + (size_t)p * (LLn * DTP);
        lda = DTP; ldb = DTP; kT = 10; NB = LLn;
    }

    const int m0 = blockIdx.x * 48, n0 = blockIdx.y * 48;
    uint32_t sbase = (uint32_t)__cvta_generic_to_shared(sm);

    const int lane = tid & 31, warp = tid >> 5;
    const int quad = lane >> 3, r = lane & 7;
    // A fragment addresses (row stride 48B, col offset 8 halves = 16B)
    uint32_t aAddr = sbase + (uint32_t)(warp * 16 + ((quad & 1) ? 8 : 0) + r) * 48
                           + ((quad >> 1) ? 16 : 0);
    // B fragment addresses
    uint32_t bAddr0 = sbase + 4608
                    + (uint32_t)(((lane >> 4) ? 8 : 0) + r) * 48
                    + ((quad & 1) ? 16 : 0);

    float acc[6][4];
    #pragma unroll
    for (int i = 0; i < 6; i++)
        #pragma unroll
        for (int j = 0; j < 4; j++) acc[i][j] = 0.f;

    for (int kt = 0; kt < kT; kt++) {
        const int k0 = kt * 16;

        // ---- stage A/B hi+lo tiles: 384 uint4 transfers, 4 per thread ----
        #pragma unroll
        for (int it = 0; it < 4; it++) {
            int idx = tid + 96 * it;
            bool isB = idx >= 192;
            int rem = isB ? idx - 192 : idx;
            int row = rem >> 2;
            int q = rem & 3;
            int part = q >> 1, half = q & 1;
            uint4 v = make_uint4(0, 0, 0, 0);
            if (isB) {
                int gr = n0 + row;
                if (gr < NB)
                    v = *(const uint4*)((part ? Bl : Bh) + (size_t)gr * ldb + k0 + half * 8);
            } else {
                int gr = m0 + row;
                v = *(const uint4*)((part ? Al : Ah) + (size_t)gr * lda + k0 + half * 8);
            }
            uint32_t off = (isB ? 4608u : 0u) + (uint32_t)part * 2304u
                         + (uint32_t)row * 48u + (uint32_t)half * 16u;
            *(uint4*)(sm + off) = v;
        }
        __syncthreads();

        // ---- fragments ----
        uint32_t ah[4], al4[4];
        ldm4(ah, aAddr);
        ldm4(al4, aAddr + 2304);

        uint32_t bh[3][4], bl[3][4];
        #pragma unroll
        for (int g = 0; g < 3; g++) {
            ldm4(bh[g], bAddr0 + (uint32_t)g * 768u);
            ldm4(bl[g], bAddr0 + (uint32_t)g * 768u + 2304u);
        }

        // ---- 18 HMMA: hi*hi + hi*lo + lo*hi ----
        #pragma unroll
        for (int g = 0; g < 3; g++) {
            mma_bf16(acc[2 * g],     ah,  bh[g][0], bh[g][1]);
            mma_bf16(acc[2 * g],     ah,  bl[g][0], bl[g][1]);
            mma_bf16(acc[2 * g],     al4, bh[g][0], bh[g][1]);
            mma_bf16(acc[2 * g + 1], ah,  bh[g][2], bh[g][3]);
            mma_bf16(acc[2 * g + 1], ah,  bl[g][2], bl[g][3]);
            mma_bf16(acc[2 * g + 1], al4, bh[g][2], bh[g][3]);
        }
        __syncthreads();
    }

    // ---- store ----
    const int g8 = lane >> 2, t2 = (lane & 3) * 2;
    #pragma unroll
    for (int nb = 0; nb < 6; nb++) {
        #pragma unroll
        for (int e = 0; e < 4; e++) {
            int m = m0 + warp * 16 + g8 + ((e >> 1) ? 8 : 0);
            int n = n0 + nb * 8 + t2 + (e & 1);
            float v = acc[nb][e];
            if constexpr (MODE == 0) {
                if (n < DTP) {
                    float val = (n < DT) ? v + bias[n] : 0.f;
                    size_t d = (size_t)m * DTP + n;
                    split2(val, g_ph[sel][d], g_pl[sel][d]);
                }
            }
            if constexpr (MODE == 1) {
                if (n < DTP) {
                    int o = p / DT, i = p % DT;
                    size_t d = ((size_t)(m * NOUT + o) * DT + i) * DTP + n;
                    split2(v, g_wh[d], g_wl[d]);
                }
            }
            if constexpr (MODE == 2) {
                if (n < DTP) {
                    size_t d = ((size_t)p * LLn + m) * DTP + n;
                    split2(v, g_th[d], g_tl[d]);
                }
            }
            if constexpr (MODE == 3) {
                int bz = p >> 2, o = p & 3;
                outp[(((size_t)bz * LLn + m) * LLn + n) * NOUT + o] = v;
            }
            if constexpr (MODE == 4) {
                int bz = p >> 2, o = p & 3;
                outp[(((size_t)bz * LLn + n) * LLn + m) * NOUT + o] = v;
            }
        }
    }
}

// ---------------- epilogue: mask + log_softmax over NOUT=4 ----------------
__global__ void epilogue_kernel(float* __restrict__ out)
{
    int e = blockIdx.x * blockDim.x + threadIdx.x;
    if (e >= TOT4) return;
    int rr = e % PEROUT;
    int x = (rr / LLn) % LLn;
    int z = (rr / (LLn * LLn)) % LLn;

    float4* p4 = (float4*)out;
    float4 v = p4[e];
    if (z > x) {
        const float c = -1.3862943611198906f;   // log(1/4)
        v.x = c; v.y = c; v.z = c; v.w = c;
    } else {
        float m = fmaxf(fmaxf(v.x, v.y), fmaxf(v.z, v.w));
        float s = expf(v.x - m) + expf(v.y - m) + expf(v.z - m) + expf(v.w - m);
        float l = m + logf(s);
        v.x -= l; v.y -= l; v.z -= l; v.w -= l;
    }
    p4[e] = v;
}

// ---------------------------------------------------------------------------
extern "C" void kernel_launch(void* const* d_in, const int* in_sizes, int n_in,
                              void* d_out, int out_size)
{
    const float* x     = (const float*)d_in[0];
    const float* W_sh  = (const float*)d_in[1];
    const float* b_sh  = (const float*)d_in[2];
    const float* W_st  = (const float*)d_in[3];
    const float* b_st  = (const float*)d_in[4];
    const float* W_oh  = (const float*)d_in[5];
    const float* b_oh  = (const float*)d_in[6];
    const float* W_ot  = (const float*)d_in[7];
    const float* b_ot  = (const float*)d_in[8];
    const float* W_t1  = (const float*)d_in[9];
    const float* W_t2  = (const float*)d_in[10];
    float* out = (float*)d_out;

    // prep: split inputs/weights into bf16 hi/lo
    prep_x<<<(BL * DIN + 255) / 256, 256>>>(x);
    prep_pw<<<(DT * DIN + 255) / 256, 256>>>(W_sh, 0);
    prep_pw<<<(DT * DIN + 255) / 256, 256>>>(W_st, 1);
    prep_pw<<<(DT * DIN + 255) / 256, 256>>>(W_oh, 2);
    prep_pw<<<(DT * DIN + 255) / 256, 256>>>(W_ot, 3);
    prep_wt<<<dim3(OI, 5, 5), dim3(32, 32)>>>(W_t1, 0);
    prep_wt<<<dim3(OI, 5, 5), dim3(32, 32)>>>(W_t2, 1);

    // projections (M=288, N->192 grid, K=1024)
    mmak<0><<<dim3(6, 4, 1), 96>>>(b_sh, nullptr, 0, 0);
    mmak<0><<<dim3(6, 4, 1), 96>>>(b_st, nullptr, 1, 0);
    mmak<0><<<dim3(6, 4, 1), 96>>>(b_oh, nullptr, 2, 0);
    mmak<0><<<dim3(6, 4, 1), 96>>>(b_ot, nullptr, 3, 0);

    // triaffine 1: (x=st[1], y=oh[2], z=sh[0], W1)
    mmak<1><<<dim3(6, 4, OI),  96>>>(nullptr, nullptr, 0, 0);  // w = sh @ Wt1
    mmak<2><<<dim3(3, 4, BZO), 96>>>(nullptr, nullptr, 2, 0);  // t = oh @ w^T
    mmak<3><<<dim3(3, 3, BZO), 96>>>(nullptr, out, 1, 0);      // s1 = st @ t^T

    // triaffine 2: (x=ot[3], y=st[1], z=sh[0], W2), transposed store
    mmak<1><<<dim3(6, 4, OI),  96>>>(nullptr, nullptr, 0, 1);  // w = sh @ Wt2
    mmak<2><<<dim3(3, 4, BZO), 96>>>(nullptr, nullptr, 1, 0);  // t = st @ w^T
    mmak<4><<<dim3(3, 3, BZO), 96>>>(nullptr, out + OUT1N, 3, 0); // s2^T

    // mask + log_softmax
    epilogue_kernel<<<(TOT4 + 255) / 256, 256>>>(out);
}